// round 15
// baseline (speedup 1.0000x reference)
#include <cuda_runtime.h>
#include <math.h>

// Problem shape (fixed by the reference): x[N,K], w[M,K], out[N,M]
#define N_ 1024
#define K_ 256
#define M_ 1024

// Scratch (allocs forbidden; __device__ globals are the sanctioned path).
// All writes are idempotent across graph replays (same inputs -> same values).
__device__ float        g_bT[K_][M_];     // bT[k][m] = |w[m][k]| (1 MB, L2-resident)
__device__ unsigned int g_bmax_bits;      // bits of max|w| (nonneg fp32 orders as uint)
__device__ float2       g_cand[N_][K_];   // per-row compacted {a, bits(k)} pairs
__device__ int          g_cnt[N_];        // per-row exact candidate count (>=1)

// ---------------------------------------------------------------------------
// Kernel 1: abs + transpose of w + Bmax (exact R8 config: 64x64 tiles,
// grid (16,4) = 64 CTAs x 256 threads, MLP=4 per thread, 1 atomic per warp).
// ---------------------------------------------------------------------------
__global__ void __launch_bounds__(256)
absT_kernel(const float* __restrict__ w) {
    __shared__ float tile[64][65];        // [k][m], +1 pad

    const int bm   = blockIdx.x * 64;
    const int bk   = blockIdx.y * 64;
    const int tid  = threadIdx.x;
    const int lane = tid & 31;

    const int k4 = tid & 15;
    const int m0 = tid >> 4;
    float lmax = 0.0f;
    #pragma unroll
    for (int i = 0; i < 4; i++) {
        const int m = m0 + i * 16;
        const float4 v = reinterpret_cast<const float4*>(
                             &w[(bm + m) * K_ + bk])[k4];
        const float a0 = fabsf(v.x), a1 = fabsf(v.y),
                    a2 = fabsf(v.z), a3 = fabsf(v.w);
        tile[4 * k4 + 0][m] = a0;
        tile[4 * k4 + 1][m] = a1;
        tile[4 * k4 + 2][m] = a2;
        tile[4 * k4 + 3][m] = a3;
        lmax = fmaxf(lmax, fmaxf(fmaxf(a0, a1), fmaxf(a2, a3)));
    }
    const unsigned int wm = __reduce_max_sync(0xffffffffu, __float_as_uint(lmax));
    if (lane == 0) atomicMax(&g_bmax_bits, wm);
    __syncthreads();

    const int m4 = tid & 15;
    const int k0 = tid >> 4;
    #pragma unroll
    for (int i = 0; i < 4; i++) {
        const int k = k0 + i * 16;
        float4 o;
        o.x = tile[k][4 * m4 + 0];
        o.y = tile[k][4 * m4 + 1];
        o.z = tile[k][4 * m4 + 2];
        o.w = tile[k][4 * m4 + 3];
        reinterpret_cast<float4*>(&g_bT[bk + k][bm])[m4] = o;
    }
}

// ---------------------------------------------------------------------------
// Kernel 2: one warp per row (exact R8 config). Exact pruning: keep k iff
// a + Bmax >= amax (fp-monotone => exact; ">=" keeps the argmax so cnt >= 1).
// Exact count, no padding. grid = 256 CTAs x 128 threads.
// ---------------------------------------------------------------------------
__global__ void __launch_bounds__(128)
candidates_kernel(const float* __restrict__ x) {
    const int lane = threadIdx.x & 31;
    const int n    = blockIdx.x * 4 + (threadIdx.x >> 5);

    const float4* xr = reinterpret_cast<const float4*>(x + n * K_);
    const float4 v0 = xr[lane * 2];
    const float4 v1 = xr[lane * 2 + 1];
    float av[8];
    av[0] = fabsf(v0.x); av[1] = fabsf(v0.y);
    av[2] = fabsf(v0.z); av[3] = fabsf(v0.w);
    av[4] = fabsf(v1.x); av[5] = fabsf(v1.y);
    av[6] = fabsf(v1.z); av[7] = fabsf(v1.w);

    float lmax = av[0];
    #pragma unroll
    for (int j = 1; j < 8; j++) lmax = fmaxf(lmax, av[j]);
    const float amax = __uint_as_float(
        __reduce_max_sync(0xffffffffu, __float_as_uint(lmax)));
    const float Bmax = __uint_as_float(g_bmax_bits);  // ordered by kernel boundary

    int base = 0;
    #pragma unroll
    for (int j = 0; j < 8; j++) {
        const bool keep = (av[j] + Bmax >= amax);
        const unsigned int bal = __ballot_sync(0xffffffffu, keep);
        if (keep) {
            const int p = base + __popc(bal & ((1u << lane) - 1u));
            g_cand[n][p] = make_float2(av[j], __int_as_float(lane * 8 + j));
        }
        base += __popc(bal);
    }
    if (lane == 0) g_cnt[n] = base;
}

// ---------------------------------------------------------------------------
// Kernel 3: the sweep. grid = 2048 CTAs x 128 threads; warp = (row, 128-m
// slice). Shfl-free inner loop: uniform LDG.128 broadcasts TWO candidates to
// the warp, then two independent bT LDG.128s. Warp-uniform tail guard only.
// ---------------------------------------------------------------------------
__global__ void __launch_bounds__(128)
sweep_kernel(float* __restrict__ out) {
    const int tid   = threadIdx.x;
    const int lane  = tid & 31;
    const int wid   = tid >> 5;
    const int n     = blockIdx.x >> 1;
    const int slice = ((blockIdx.x & 1) << 2) | wid;  // 0..7

    const int cnt = g_cnt[n];                          // uniform LDG, exact

    const float4* const bbase =
        reinterpret_cast<const float4*>(g_bT) + slice * 32 + lane;
    const float4* const candv =
        reinterpret_cast<const float4*>(g_cand[n]);    // 2 candidates per load

    float4 acc0 = make_float4(-INFINITY, -INFINITY, -INFINITY, -INFINITY);
    float4 acc1 = acc0;

    #pragma unroll 2
    for (int j = 0; j < cnt; j += 2) {
        const float4 q = candv[j >> 1];                // uniform broadcast LDG.128
        {
            const float4 v = bbase[__float_as_int(q.y) * (M_ / 4)];
            acc0.x = fmaxf(acc0.x, q.x + v.x);
            acc0.y = fmaxf(acc0.y, q.x + v.y);
            acc0.z = fmaxf(acc0.z, q.x + v.z);
            acc0.w = fmaxf(acc0.w, q.x + v.w);
        }
        if (j + 1 < cnt) {                             // warp-uniform guard
            const float4 v = bbase[__float_as_int(q.w) * (M_ / 4)];
            acc1.x = fmaxf(acc1.x, q.z + v.x);
            acc1.y = fmaxf(acc1.y, q.z + v.y);
            acc1.z = fmaxf(acc1.z, q.z + v.z);
            acc1.w = fmaxf(acc1.w, q.z + v.w);
        }
    }

    float4 r;
    r.x = fmaxf(acc0.x, acc1.x);
    r.y = fmaxf(acc0.y, acc1.y);
    r.z = fmaxf(acc0.z, acc1.z);
    r.w = fmaxf(acc0.w, acc1.w);
    reinterpret_cast<float4*>(out + n * M_)[slice * 32 + lane] = r;
}

// ---------------------------------------------------------------------------
extern "C" void kernel_launch(void* const* d_in, const int* in_sizes, int n_in,
                              void* d_out, int out_size) {
    const float* x = (const float*)d_in[0];   // [N, K] fp32
    const float* w = (const float*)d_in[1];   // [M, K] fp32
    float* out     = (float*)d_out;           // [N, M] fp32

    (void)in_sizes; (void)n_in; (void)out_size;

    absT_kernel<<<dim3(M_ / 64, K_ / 64), 256>>>(w);
    candidates_kernel<<<N_ / 4, 128>>>(x);
    sweep_kernel<<<2 * N_, 128>>>(out);
}

// round 16
// speedup vs baseline: 1.2035x; 1.2035x over previous
#include <cuda_runtime.h>
#include <math.h>

// Problem shape (fixed by the reference): x[N,K], w[M,K], out[N,M]
#define N_ 1024
#define K_ 256
#define M_ 1024

// Scratch (allocs forbidden; __device__ globals are the sanctioned path).
// All writes are idempotent across graph replays (same inputs -> same values).
__device__ float        g_bT[K_][M_];     // bT[k][m] = |w[m][k]| (1 MB, L2-resident)
__device__ unsigned int g_bmax_bits;      // bits of max|w| (nonneg fp32 orders as uint)
__device__ float2       g_cand[N_][K_];   // per-row compacted {a, bits(k)} pairs
__device__ int          g_cnt[N_];        // per-row exact candidate count (>=1)

// ---------------------------------------------------------------------------
// Kernel 1: abs + transpose of w + Bmax (R8 champion config: 64x64 tiles,
// grid (16,4) = 64 CTAs x 256 threads, MLP=4 per thread, 1 atomic per warp).
// ---------------------------------------------------------------------------
__global__ void __launch_bounds__(256)
absT_kernel(const float* __restrict__ w) {
    __shared__ float tile[64][65];        // [k][m], +1 pad

    const int bm   = blockIdx.x * 64;
    const int bk   = blockIdx.y * 64;
    const int tid  = threadIdx.x;
    const int lane = tid & 31;

    const int k4 = tid & 15;
    const int m0 = tid >> 4;
    float lmax = 0.0f;
    #pragma unroll
    for (int i = 0; i < 4; i++) {
        const int m = m0 + i * 16;
        const float4 v = reinterpret_cast<const float4*>(
                             &w[(bm + m) * K_ + bk])[k4];
        const float a0 = fabsf(v.x), a1 = fabsf(v.y),
                    a2 = fabsf(v.z), a3 = fabsf(v.w);
        tile[4 * k4 + 0][m] = a0;
        tile[4 * k4 + 1][m] = a1;
        tile[4 * k4 + 2][m] = a2;
        tile[4 * k4 + 3][m] = a3;
        lmax = fmaxf(lmax, fmaxf(fmaxf(a0, a1), fmaxf(a2, a3)));
    }
    const unsigned int wm = __reduce_max_sync(0xffffffffu, __float_as_uint(lmax));
    if (lane == 0) atomicMax(&g_bmax_bits, wm);
    __syncthreads();

    const int m4 = tid & 15;
    const int k0 = tid >> 4;
    #pragma unroll
    for (int i = 0; i < 4; i++) {
        const int k = k0 + i * 16;
        float4 o;
        o.x = tile[k][4 * m4 + 0];
        o.y = tile[k][4 * m4 + 1];
        o.z = tile[k][4 * m4 + 2];
        o.w = tile[k][4 * m4 + 3];
        reinterpret_cast<float4*>(&g_bT[bk + k][bm])[m4] = o;
    }
}

// ---------------------------------------------------------------------------
// Kernel 2: one warp per row (R8 champion config). Exact pruning: keep k iff
// a + Bmax >= amax (fp-monotone => exact; ">=" keeps the argmax so cnt >= 1).
// Exact count, no padding. grid = 256 CTAs x 128 threads.
// ---------------------------------------------------------------------------
__global__ void __launch_bounds__(128)
candidates_kernel(const float* __restrict__ x) {
    const int lane = threadIdx.x & 31;
    const int n    = blockIdx.x * 4 + (threadIdx.x >> 5);

    const float4* xr = reinterpret_cast<const float4*>(x + n * K_);
    const float4 v0 = xr[lane * 2];
    const float4 v1 = xr[lane * 2 + 1];
    float av[8];
    av[0] = fabsf(v0.x); av[1] = fabsf(v0.y);
    av[2] = fabsf(v0.z); av[3] = fabsf(v0.w);
    av[4] = fabsf(v1.x); av[5] = fabsf(v1.y);
    av[6] = fabsf(v1.z); av[7] = fabsf(v1.w);

    float lmax = av[0];
    #pragma unroll
    for (int j = 1; j < 8; j++) lmax = fmaxf(lmax, av[j]);
    const float amax = __uint_as_float(
        __reduce_max_sync(0xffffffffu, __float_as_uint(lmax)));
    const float Bmax = __uint_as_float(g_bmax_bits);  // ordered by kernel boundary

    int base = 0;
    #pragma unroll
    for (int j = 0; j < 8; j++) {
        const bool keep = (av[j] + Bmax >= amax);
        const unsigned int bal = __ballot_sync(0xffffffffu, keep);
        if (keep) {
            const int p = base + __popc(bal & ((1u << lane) - 1u));
            g_cand[n][p] = make_float2(av[j], __int_as_float(lane * 8 + j));
        }
        base += __popc(bal);
    }
    if (lane == 0) g_cnt[n] = base;
}

// ---------------------------------------------------------------------------
// Kernel 3: the sweep (R8 champion structure). grid = 2048 CTAs x 128
// threads; warp = (row, 128-m slice). ONE change vs R8: the first candidate
// block is loaded UNCONDITIONALLY, in parallel with the cnt load (both
// addresses known at warp start) -> one fewer serialized L2 latency per
// warp. Reads past cnt are deterministic (device global) and never consumed.
// ---------------------------------------------------------------------------
__global__ void __launch_bounds__(128)
sweep_kernel(float* __restrict__ out) {
    const int tid   = threadIdx.x;
    const int lane  = tid & 31;
    const int wid   = tid >> 5;
    const int n     = blockIdx.x >> 1;
    const int slice = ((blockIdx.x & 1) << 2) | wid;  // 0..7

    const float2* const cand = g_cand[n];

    // issue BOTH loads back-to-back: no dependence between them
    const float2 p0 = cand[lane];                      // first 32 candidates
    const int   cnt = g_cnt[n];                        // uniform LDG, exact

    const float4* const bbase =
        reinterpret_cast<const float4*>(g_bT) + slice * 32 + lane;
    float4 acc = make_float4(-INFINITY, -INFINITY, -INFINITY, -INFINITY);

    // first block: shfl-distributed, all bT loads independent after p0
    {
        const int lim = min(32, cnt);
        for (int j = 0; j < lim; j++) {
            const float aj = __shfl_sync(0xffffffffu, p0.x, j);
            const int   kj = __float_as_int(__shfl_sync(0xffffffffu, p0.y, j));
            const float4 v = bbase[kj * (M_ / 4)];     // coalesced, independent
            acc.x = fmaxf(acc.x, aj + v.x);
            acc.y = fmaxf(acc.y, aj + v.y);
            acc.z = fmaxf(acc.z, aj + v.z);
            acc.w = fmaxf(acc.w, aj + v.w);
        }
    }

    // continuation (cnt > 32 is statistically near-impossible; exact anyway)
    for (int b = 32; b < cnt; b += 32) {
        const int lim = min(32, cnt - b);
        float2 p = make_float2(0.0f, 0.0f);
        if (lane < lim) p = cand[b + lane];
        for (int j = 0; j < lim; j++) {
            const float aj = __shfl_sync(0xffffffffu, p.x, j);
            const int   kj = __float_as_int(__shfl_sync(0xffffffffu, p.y, j));
            const float4 v = bbase[kj * (M_ / 4)];
            acc.x = fmaxf(acc.x, aj + v.x);
            acc.y = fmaxf(acc.y, aj + v.y);
            acc.z = fmaxf(acc.z, aj + v.z);
            acc.w = fmaxf(acc.w, aj + v.w);
        }
    }

    reinterpret_cast<float4*>(out + n * M_)[slice * 32 + lane] = acc;
}

// ---------------------------------------------------------------------------
extern "C" void kernel_launch(void* const* d_in, const int* in_sizes, int n_in,
                              void* d_out, int out_size) {
    const float* x = (const float*)d_in[0];   // [N, K] fp32
    const float* w = (const float*)d_in[1];   // [M, K] fp32
    float* out     = (float*)d_out;           // [N, M] fp32

    (void)in_sizes; (void)n_in; (void)out_size;

    absT_kernel<<<dim3(M_ / 64, K_ / 64), 256>>>(w);
    candidates_kernel<<<N_ / 4, 128>>>(x);
    sweep_kernel<<<2 * N_, 128>>>(out);
}